// round 2
// baseline (speedup 1.0000x reference)
#include <cuda_runtime.h>

// Problem constants
#define NCTA 128
#define NTHR 256
#define BB   64      // batch
#define TT   512     // timesteps
#define DIN  64      // input dim
#define HH   512     // hidden
#define KC   128     // K chunk
#define HP   129     // smem row pitch (floats), odd-ish for bank spread

// Persistent state (device globals; no cudaMalloc allowed)
__device__ float    g_h1[2][BB * HH];
__device__ float    g_h2[2][BB * HH];
__device__ unsigned g_bar;

__device__ __forceinline__ float sigm(float x)      { return 1.f / (1.f + __expf(-x)); }
__device__ __forceinline__ float tanh_fast(float x) { return 2.f / (1.f + __expf(-2.f * x)) - 1.f; }

__global__ void init_kernel() {
    unsigned i = blockIdx.x * blockDim.x + threadIdx.x;
    if (i == 0) g_bar = 0u;
    if (i < BB * HH) { g_h1[0][i] = 0.f; g_h2[0][i] = 0.f; }
}

// Monotonic-target grid barrier (counter reset by init_kernel each launch).
__device__ __forceinline__ void gbar(unsigned target) {
    __syncthreads();
    if (threadIdx.x == 0) {
        __threadfence();
        atomicAdd(&g_bar, 1u);
        while (*((volatile unsigned*)&g_bar) < target) { }
        __threadfence();
    }
    __syncthreads();
}

// Stage h-chunk: src[b][kc + k] (row stride ld) -> h_s[b*HP + k], b<64, k<kn (kn = 1<<klog)
__device__ __forceinline__ void load_h(float* h_s, const float* __restrict__ src,
                                       int ld, int kc, int kn, int klog, int tid) {
    for (int idx = tid; idx < BB * kn; idx += NTHR) {
        int b = idx >> klog;
        int k = idx & (kn - 1);
        h_s[b * HP + k] = src[b * ld + kc + k];
    }
}

// Stage W-chunk: 16 gate-rows for this CTA's 4 units.
// smem row r = ju*4 + g  maps to global row g*HH + j0 + ju.
__device__ __forceinline__ void load_w(const float* __restrict__ W, float* W_s,
                                       int ld, int kc, int kn, int klog, int j0, int tid) {
    for (int idx = tid; idx < 16 * kn; idx += NTHR) {
        int r = idx >> klog;
        int k = idx & (kn - 1);
        int wju = r >> 2;
        int g   = r & 3;
        W_s[r * HP + k] = W[(g * HH + j0 + wju) * ld + kc + k];
    }
}

// Per-thread: 4 gates x 8 batches accumulate over this warp's K slice.
// Thread coords: ks = warp (K split 8-way), ju = unit (4), boct = batch phase (8);
// thread's batches are {boct, boct+8, ..., boct+56} (consecutive smem rows across
// lanes -> conflict-free h reads; W reads land on banks {0,4,8,12} -> conflict-free).
__device__ __forceinline__ void mm_chunk(float acc[4][8], const float* h_s, const float* W_s,
                                         int kn, int ks, int ju, int boct) {
    int k0   = ks * (kn >> 3);
    int kend = k0 + (kn >> 3);
#pragma unroll 4
    for (int k = k0; k < kend; ++k) {
        float w0 = W_s[(ju * 4 + 0) * HP + k];
        float w1 = W_s[(ju * 4 + 1) * HP + k];
        float w2 = W_s[(ju * 4 + 2) * HP + k];
        float w3 = W_s[(ju * 4 + 3) * HP + k];
#pragma unroll
        for (int i = 0; i < 8; ++i) {
            float hv = h_s[(boct + 8 * i) * HP + k];
            acc[0][i] = fmaf(w0, hv, acc[0][i]);
            acc[1][i] = fmaf(w1, hv, acc[1][i]);
            acc[2][i] = fmaf(w2, hv, acc[2][i]);
            acc[3][i] = fmaf(w3, hv, acc[3][i]);
        }
    }
}

__global__ void __launch_bounds__(NTHR, 1) lstm_kernel(
    const float* __restrict__ x,
    const float* __restrict__ Wih0, const float* __restrict__ Whh0,
    const float* __restrict__ bih0, const float* __restrict__ bhh0,
    const float* __restrict__ Wih1, const float* __restrict__ Whh1,
    const float* __restrict__ bih1, const float* __restrict__ bhh1,
    const float* __restrict__ fcw,  const float* __restrict__ fcb,
    float* __restrict__ out)
{
    __shared__ float sm[(BB + 16) * HP];   // 41,280 B: h_s(64 rows) + W_s(16 rows); red overlays
    float* h_s = sm;
    float* W_s = sm + BB * HP;
    float* red = sm;                        // 128 rows x 65 = 8320 floats, fits in pool

    const int tid  = threadIdx.x;
    const int cta  = blockIdx.x;
    const int ks   = tid >> 5;        // warp id = K-split id (0..7)
    const int lane = tid & 31;
    const int ju   = lane >> 3;       // unit-local (0..3)
    const int boct = lane & 7;        // batch phase (0..7)
    const int eb   = tid & 63;        // epilogue batch
    const int ejl  = tid >> 6;        // epilogue unit-local
    const int ej   = cta * 4 + ejl;   // epilogue global unit
    const int j0   = cta * 4;

    float bias0[4], bias1[4];
#pragma unroll
    for (int g = 0; g < 4; ++g) {
        bias0[g] = bih0[g * HH + ej] + bhh0[g * HH + ej];
        bias1[g] = bih1[g * HH + ej] + bhh1[g * HH + ej];
    }
    float c1 = 0.f, c2 = 0.f;
    unsigned bar_i = 0;
    float acc[4][8];

    for (int t = 0; t < TT; ++t) {
        const int p = t & 1;

        // ======== Layer 0: gates = x_t @ Wih0^T + h1[p] @ Whh0^T ========
#pragma unroll
        for (int g = 0; g < 4; ++g)
#pragma unroll
            for (int i = 0; i < 8; ++i) acc[g][i] = 0.f;

        __syncthreads();
        load_h(h_s, x + t * DIN, TT * DIN, 0, DIN, 6, tid);
        load_w(Wih0, W_s, DIN, 0, DIN, 6, j0, tid);
        __syncthreads();
        mm_chunk(acc, h_s, W_s, DIN, ks, ju, boct);

        for (int kc = 0; kc < HH; kc += KC) {
            __syncthreads();
            load_h(h_s, g_h1[p], HH, kc, KC, 7, tid);
            load_w(Whh0, W_s, HH, kc, KC, 7, j0, tid);
            __syncthreads();
            mm_chunk(acc, h_s, W_s, KC, ks, ju, boct);
        }

        // K-split reduction + LSTM cell epilogue (layer 0)
        __syncthreads();
#pragma unroll
        for (int g = 0; g < 4; ++g)
#pragma unroll
            for (int i = 0; i < 8; ++i)
                red[((ks * 4 + g) * 4 + ju) * 65 + boct + 8 * i] = acc[g][i];
        __syncthreads();
        {
            float s0 = 0.f, s1 = 0.f, s2 = 0.f, s3 = 0.f;
#pragma unroll
            for (int kk = 0; kk < 8; ++kk) {
                s0 += red[((kk * 4 + 0) * 4 + ejl) * 65 + eb];
                s1 += red[((kk * 4 + 1) * 4 + ejl) * 65 + eb];
                s2 += red[((kk * 4 + 2) * 4 + ejl) * 65 + eb];
                s3 += red[((kk * 4 + 3) * 4 + ejl) * 65 + eb];
            }
            float ig = sigm(s0 + bias0[0]);
            float fg = sigm(s1 + bias0[1]);
            float gv = tanh_fast(s2 + bias0[2]);
            float og = sigm(s3 + bias0[3]);
            c1 = fg * c1 + ig * gv;
            g_h1[1 - p][eb * HH + ej] = og * tanh_fast(c1);
        }
        gbar(++bar_i * NCTA);

        // ======== Layer 1: gates = h1[1-p] @ Wih1^T + h2[p] @ Whh1^T ========
#pragma unroll
        for (int g = 0; g < 4; ++g)
#pragma unroll
            for (int i = 0; i < 8; ++i) acc[g][i] = 0.f;

        for (int kc = 0; kc < HH; kc += KC) {
            __syncthreads();
            load_h(h_s, g_h1[1 - p], HH, kc, KC, 7, tid);
            load_w(Wih1, W_s, HH, kc, KC, 7, j0, tid);
            __syncthreads();
            mm_chunk(acc, h_s, W_s, KC, ks, ju, boct);
        }
        for (int kc = 0; kc < HH; kc += KC) {
            __syncthreads();
            load_h(h_s, g_h2[p], HH, kc, KC, 7, tid);
            load_w(Whh1, W_s, HH, kc, KC, 7, j0, tid);
            __syncthreads();
            mm_chunk(acc, h_s, W_s, KC, ks, ju, boct);
        }

        __syncthreads();
#pragma unroll
        for (int g = 0; g < 4; ++g)
#pragma unroll
            for (int i = 0; i < 8; ++i)
                red[((ks * 4 + g) * 4 + ju) * 65 + boct + 8 * i] = acc[g][i];
        __syncthreads();
        {
            float s0 = 0.f, s1 = 0.f, s2 = 0.f, s3 = 0.f;
#pragma unroll
            for (int kk = 0; kk < 8; ++kk) {
                s0 += red[((kk * 4 + 0) * 4 + ejl) * 65 + eb];
                s1 += red[((kk * 4 + 1) * 4 + ejl) * 65 + eb];
                s2 += red[((kk * 4 + 2) * 4 + ejl) * 65 + eb];
                s3 += red[((kk * 4 + 3) * 4 + ejl) * 65 + eb];
            }
            float ig = sigm(s0 + bias1[0]);
            float fg = sigm(s1 + bias1[1]);
            float gv = tanh_fast(s2 + bias1[2]);
            float og = sigm(s3 + bias1[3]);
            c2 = fg * c2 + ig * gv;
            g_h2[1 - p][eb * HH + ej] = og * tanh_fast(c2);
        }
        gbar(++bar_i * NCTA);
    }

    // FC head on last h2 (T even -> final state in buffer 0)
    if (cta == 0 && tid < BB) {
        const float* hf = g_h2[0];
        float a = fcb[0];
        for (int j = 0; j < HH; ++j) a = fmaf(hf[tid * HH + j], fcw[j], a);
        out[tid] = a;
    }
}

extern "C" void kernel_launch(void* const* d_in, const int* in_sizes, int n_in,
                              void* d_out, int out_size) {
    (void)in_sizes; (void)n_in; (void)out_size;
    const float* x    = (const float*)d_in[0];
    const float* Wih0 = (const float*)d_in[1];
    const float* Whh0 = (const float*)d_in[2];
    const float* bih0 = (const float*)d_in[3];
    const float* bhh0 = (const float*)d_in[4];
    const float* Wih1 = (const float*)d_in[5];
    const float* Whh1 = (const float*)d_in[6];
    const float* bih1 = (const float*)d_in[7];
    const float* bhh1 = (const float*)d_in[8];
    const float* fcw  = (const float*)d_in[9];
    const float* fcb  = (const float*)d_in[10];
    float* out = (float*)d_out;

    init_kernel<<<(BB * HH + NTHR - 1) / NTHR, NTHR>>>();
    lstm_kernel<<<NCTA, NTHR>>>(x, Wih0, Whh0, bih0, bhh0,
                                Wih1, Whh1, bih1, bhh1, fcw, fcb, out);
}

// round 3
// speedup vs baseline: 1.2229x; 1.2229x over previous
#include <cuda_runtime.h>

#define NCTA 128
#define NTHR 256
#define BB   64      // batch
#define TT   512     // timesteps
#define DIN  64      // input dim
#define HH   512     // hidden
#define HP   576     // per-batch smem pitch (floats): 16 slices x 36
#define RP   68      // red pitch

// Persistent state (device globals; no cudaMalloc allowed)
__device__ float    g_h1[2][BB * HH];
__device__ float    g_h2[2][BB * HH];
__device__ unsigned g_bar;

typedef unsigned long long ull;

__device__ __forceinline__ float sigm(float x)      { return 1.f / (1.f + __expf(-x)); }
__device__ __forceinline__ float tanh_fast(float x) { return 2.f / (1.f + __expf(-2.f * x)) - 1.f; }

__device__ __forceinline__ ull f2(ull a, ull b, ull c) {
    ull d;
    asm("fma.rn.f32x2 %0, %1, %2, %3;" : "=l"(d) : "l"(a), "l"(b), "l"(c));
    return d;
}
__device__ __forceinline__ ull packf2(float x, float y) {
    return (ull)__float_as_uint(x) | ((ull)__float_as_uint(y) << 32);
}
__device__ __forceinline__ float f2lo(ull a) { return __uint_as_float((unsigned)a); }
__device__ __forceinline__ float f2hi(ull a) { return __uint_as_float((unsigned)(a >> 32)); }

__global__ void init_kernel() {
    unsigned i = blockIdx.x * blockDim.x + threadIdx.x;
    if (i == 0) g_bar = 0u;
    if (i < BB * HH) { g_h1[0][i] = 0.f; g_h2[0][i] = 0.f; }
}

// Monotonic-target grid barrier (counter reset by init_kernel each launch).
// __threadfence (gpu scope) also flushes this SM's L1D (CCTL.IVALL), so
// post-barrier plain loads of peer-written h are coherent.
__device__ __forceinline__ void gbar(unsigned target) {
    __syncthreads();
    if (threadIdx.x == 0) {
        __threadfence();
        atomicAdd(&g_bar, 1u);
        while (*((volatile unsigned*)&g_bar) < target) { }
        __threadfence();
    }
    __syncthreads();
}

__global__ void __launch_bounds__(NTHR, 1) lstm_kernel(
    const float* __restrict__ x,
    const float* __restrict__ Wih0, const float* __restrict__ Whh0,
    const float* __restrict__ bih0, const float* __restrict__ bhh0,
    const float* __restrict__ Wih1, const float* __restrict__ Whh1,
    const float* __restrict__ bih1, const float* __restrict__ bhh1,
    const float* __restrict__ fcw,  const float* __restrict__ fcb,
    float* __restrict__ out)
{
    extern __shared__ float sm[];        // h area: BB*HP floats, then red: 16*RP
    float* red = sm + BB * HP;

    const int tid = threadIdx.x;
    const int cta = blockIdx.x;
    const int r   = tid >> 4;            // gate-row within CTA (0..15)
    const int s   = tid & 15;            // K-slice (0..15)
    const int u   = r >> 2;              // unit-local
    const int g   = r & 3;               // gate (i,f,g,o)
    const int grow = g * HH + cta * 4 + u;

    // ---- Register-resident weights for the whole run ----
    // L0: concat K = [h1(512) | x(64)] = 576; slice = 36 floats (18 f32x2 pairs)
    ull w0[18], w1a[16], w1b[16];
#pragma unroll
    for (int j = 0; j < 18; ++j) {
        int k = s * 36 + 2 * j;
        float f0 = (k     < HH) ? Whh0[grow * HH + k]     : Wih0[grow * DIN + (k - HH)];
        float f1 = (k + 1 < HH) ? Whh0[grow * HH + k + 1] : Wih0[grow * DIN + (k + 1 - HH)];
        w0[j] = packf2(f0, f1);
    }
#pragma unroll
    for (int j = 0; j < 16; ++j) {
        int k = s * 32 + 2 * j;
        w1a[j] = packf2(Wih1[grow * HH + k], Wih1[grow * HH + k + 1]);
        w1b[j] = packf2(Whh1[grow * HH + k], Whh1[grow * HH + k + 1]);
    }

    // Epilogue mapping: 4 units x 64 batches
    const int eb = tid & 63;
    const int eu = tid >> 6;
    const int ej = cta * 4 + eu;
    float bias0[4], bias1[4];
#pragma unroll
    for (int gg = 0; gg < 4; ++gg) {
        bias0[gg] = bih0[gg * HH + ej] + bhh0[gg * HH + ej];
        bias1[gg] = bih1[gg * HH + ej] + bhh1[gg * HH + ej];
    }

    float c1 = 0.f, c2 = 0.f;
    unsigned bi = 0;

    for (int t = 0; t < TT; ++t) {
        const int p = t & 1;

        // ======== stage L0 input: [h1[p] | x_t] contiguous, pitch HP ========
        __syncthreads();
        {
            const float4* hsrc = (const float4*)g_h1[p];
            for (int idx = tid; idx < BB * 144; idx += NTHR) {
                int b = idx / 144;
                int q = idx - b * 144;
                float4 v;
                if (q < 128) v = hsrc[b * 128 + q];
                else         v = *(const float4*)&x[(b * TT + t) * DIN + (q - 128) * 4];
                *(float4*)(sm + b * HP + q * 4) = v;
            }
        }
        __syncthreads();

        // ======== compute L0 gates ========
#pragma unroll 2
        for (int b = 0; b < BB; ++b) {
            const ulonglong2* hp = (const ulonglong2*)(sm + b * HP + s * 36);
            ull a = 0ull;
#pragma unroll
            for (int j = 0; j < 9; ++j) {
                ulonglong2 hv = hp[j];
                a = f2(w0[2 * j],     hv.x, a);
                a = f2(w0[2 * j + 1], hv.y, a);
            }
            float sum = f2lo(a) + f2hi(a);
            sum += __shfl_xor_sync(0xFFFFFFFFu, sum, 1, 16);
            sum += __shfl_xor_sync(0xFFFFFFFFu, sum, 2, 16);
            sum += __shfl_xor_sync(0xFFFFFFFFu, sum, 4, 16);
            sum += __shfl_xor_sync(0xFFFFFFFFu, sum, 8, 16);
            if (s == (b & 15)) red[r * RP + b] = sum;
        }
        __syncthreads();

        // ======== epilogue L0: cell update, write h1[1-p] ========
        {
            float ig = sigm(red[(eu * 4 + 0) * RP + eb] + bias0[0]);
            float fg = sigm(red[(eu * 4 + 1) * RP + eb] + bias0[1]);
            float gv = tanh_fast(red[(eu * 4 + 2) * RP + eb] + bias0[2]);
            float og = sigm(red[(eu * 4 + 3) * RP + eb] + bias0[3]);
            c1 = fg * c1 + ig * gv;
            g_h1[1 - p][eb * HH + ej] = og * tanh_fast(c1);
        }

        gbar(++bi * NCTA);   // single grid barrier per step

        // ======== stage L1a: h1[1-p], skewed 32-data + 4-pad slices ========
        {
            const float4* hsrc = (const float4*)g_h1[1 - p];
            for (int idx = tid; idx < BB * 128; idx += NTHR) {
                int b = idx >> 7, q = idx & 127;
                *(float4*)(sm + b * HP + (q >> 3) * 36 + (q & 7) * 4) = hsrc[idx];
            }
        }
        __syncthreads();

        // ======== compute L1a: Wih1 . h1_new ========
#pragma unroll 2
        for (int b = 0; b < BB; ++b) {
            const ulonglong2* hp = (const ulonglong2*)(sm + b * HP + s * 36);
            ull a = 0ull;
#pragma unroll
            for (int j = 0; j < 8; ++j) {
                ulonglong2 hv = hp[j];
                a = f2(w1a[2 * j],     hv.x, a);
                a = f2(w1a[2 * j + 1], hv.y, a);
            }
            float sum = f2lo(a) + f2hi(a);
            sum += __shfl_xor_sync(0xFFFFFFFFu, sum, 1, 16);
            sum += __shfl_xor_sync(0xFFFFFFFFu, sum, 2, 16);
            sum += __shfl_xor_sync(0xFFFFFFFFu, sum, 4, 16);
            sum += __shfl_xor_sync(0xFFFFFFFFu, sum, 8, 16);
            if (s == (b & 15)) red[r * RP + b] = sum;
        }
        __syncthreads();

        // ======== stage L1b: h2[p], same skew ========
        {
            const float4* hsrc = (const float4*)g_h2[p];
            for (int idx = tid; idx < BB * 128; idx += NTHR) {
                int b = idx >> 7, q = idx & 127;
                *(float4*)(sm + b * HP + (q >> 3) * 36 + (q & 7) * 4) = hsrc[idx];
            }
        }
        __syncthreads();

        // ======== compute L1b: Whh1 . h2, accumulate into red ========
#pragma unroll 2
        for (int b = 0; b < BB; ++b) {
            const ulonglong2* hp = (const ulonglong2*)(sm + b * HP + s * 36);
            ull a = 0ull;
#pragma unroll
            for (int j = 0; j < 8; ++j) {
                ulonglong2 hv = hp[j];
                a = f2(w1b[2 * j],     hv.x, a);
                a = f2(w1b[2 * j + 1], hv.y, a);
            }
            float sum = f2lo(a) + f2hi(a);
            sum += __shfl_xor_sync(0xFFFFFFFFu, sum, 1, 16);
            sum += __shfl_xor_sync(0xFFFFFFFFu, sum, 2, 16);
            sum += __shfl_xor_sync(0xFFFFFFFFu, sum, 4, 16);
            sum += __shfl_xor_sync(0xFFFFFFFFu, sum, 8, 16);
            if (s == (b & 15)) red[r * RP + b] += sum;
        }
        __syncthreads();

        // ======== epilogue L1: cell update, write h2[1-p] ========
        {
            float ig = sigm(red[(eu * 4 + 0) * RP + eb] + bias1[0]);
            float fg = sigm(red[(eu * 4 + 1) * RP + eb] + bias1[1]);
            float gv = tanh_fast(red[(eu * 4 + 2) * RP + eb] + bias1[2]);
            float og = sigm(red[(eu * 4 + 3) * RP + eb] + bias1[3]);
            c2 = fg * c2 + ig * gv;
            g_h2[1 - p][eb * HH + ej] = og * tanh_fast(c2);
        }
        // loop-top __syncthreads orders red/sm reuse
    }

    gbar(++bi * NCTA);

    // FC head on last h2 (T even -> final state in buffer 0)
    if (cta == 0 && tid < BB) {
        const float* hf = g_h2[0];
        float a = fcb[0];
        for (int j = 0; j < HH; ++j) a = fmaf(hf[tid * HH + j], fcw[j], a);
        out[tid] = a;
    }
}

extern "C" void kernel_launch(void* const* d_in, const int* in_sizes, int n_in,
                              void* d_out, int out_size) {
    (void)in_sizes; (void)n_in; (void)out_size;
    const float* x    = (const float*)d_in[0];
    const float* Wih0 = (const float*)d_in[1];
    const float* Whh0 = (const float*)d_in[2];
    const float* bih0 = (const float*)d_in[3];
    const float* bhh0 = (const float*)d_in[4];
    const float* Wih1 = (const float*)d_in[5];
    const float* Whh1 = (const float*)d_in[6];
    const float* bih1 = (const float*)d_in[7];
    const float* bhh1 = (const float*)d_in[8];
    const float* fcw  = (const float*)d_in[9];
    const float* fcb  = (const float*)d_in[10];
    float* out = (float*)d_out;

    const int smem_bytes = (BB * HP + 16 * RP) * (int)sizeof(float);  // ~151.8 KB
    cudaFuncSetAttribute(lstm_kernel, cudaFuncAttributeMaxDynamicSharedMemorySize, smem_bytes);

    init_kernel<<<(BB * HH + NTHR - 1) / NTHR, NTHR>>>();
    lstm_kernel<<<NCTA, NTHR, smem_bytes>>>(x, Wih0, Whh0, bih0, bhh0,
                                            Wih1, Whh1, bih1, bhh1, fcw, fcb, out);
}